// round 3
// baseline (speedup 1.0000x reference)
#include <cuda_runtime.h>
#include <cstdint>

#define T_STEPS 200

// ---------------- scratch (device globals: allocation-free) ----------------
__device__ float g_p[(size_t)T_STEPS * 1152 * 64];   // pooled acts [t][k][b], ~59MB
__device__ float g_s3[3 * 256 * 64];                  // conv3 spike ring [slot][oc][b]
__device__ float g_sr[2 * 256 * 64];                  // recurrent spikes, double buffered
__device__ float g_sf[128 * 64];                      // fc1 spikes
__device__ unsigned g_cnt = 0;
__device__ volatile unsigned g_gen = 0;

__device__ __forceinline__ void gridbar(unsigned n) {
    __syncthreads();
    if (threadIdx.x == 0) {
        unsigned gen = g_gen;
        __threadfence();
        if (atomicAdd(&g_cnt, 1u) == n - 1u) {
            g_cnt = 0;
            __threadfence();
            g_gen = gen + 1u;
        } else {
            while (g_gen == gen) { }
        }
        __threadfence();
    }
    __syncthreads();
}

// LIF update, unfused rounding to mirror XLA elementwise semantics:
//   cur  = 0.5*cur + psp        (mul, then add — separately rounded)
//   volt = (0.75*volt)*(1-spk) + cur
//   spk  = volt > 0.5
__device__ __forceinline__ void lif_update(float psp, float& cur, float& volt, float& spk) {
    cur  = __fadd_rn(__fmul_rn(0.5f, cur), psp);
    volt = __fadd_rn(__fmul_rn(__fmul_rn(0.75f, volt), __fadd_rn(1.f, -spk)), cur);
    spk  = (volt > 0.5f) ? 1.f : 0.f;
}

// ============================================================================
// Phase A: conv1 -> LIF -> conv2 -> LIF -> avgpool, per batch, all timesteps.
// grid = 128 CTAs (2 per batch: h = output-channel half of conv2), 256 threads.
// ============================================================================
#define A_XS    0        // 100
#define A_W1S   100      // 576
#define A_B1S   676      // 64
#define A_B2S   740      // 64
#define A_S1S   804      // 64*65 = 4160 (padded channel stride 65)
#define A_S2S   4964     // 64*36 = 2304
#define A_CUR2  7268     // 2304
#define A_VOLT2 9572     // 2304
#define A_W2S   11876    // 576*64 = 36864  (layout [ic*9+kk][oc_local])
#define A_TOT   48740    // floats -> 194960 bytes

__global__ __launch_bounds__(256, 1)
void phaseA_kernel(const float* __restrict__ input,
                   const float* __restrict__ w1, const float* __restrict__ b1,
                   const float* __restrict__ w2, const float* __restrict__ b2)
{
    extern __shared__ float sm[];
    float* xs    = sm + A_XS;
    float* w1s   = sm + A_W1S;
    float* b1s   = sm + A_B1S;
    float* b2s   = sm + A_B2S;
    float* s1s   = sm + A_S1S;
    float* s2s   = sm + A_S2S;
    float* cur2  = sm + A_CUR2;
    float* volt2 = sm + A_VOLT2;
    float* w2s   = sm + A_W2S;

    const int tid = threadIdx.x;
    const int b   = blockIdx.x >> 1;
    const int h   = blockIdx.x & 1;

    // ---- one-time staging ----
    for (int g = tid; g < 36864; g += 256) {
        int oc = g / 576;
        int r  = g - oc * 576;
        w2s[r * 64 + oc] = w2[h * 36864 + g];
    }
    for (int g = tid; g < 576; g += 256) w1s[g] = w1[g];
    if (tid < 64) { b1s[tid] = b1[tid]; b2s[tid] = b2[h * 64 + tid]; }
    for (int g = tid; g < 4160; g += 256) s1s[g] = 0.f;
    for (int g = tid; g < 2304; g += 256) { s2s[g] = 0.f; cur2[g] = 0.f; volt2[g] = 0.f; }
    __syncthreads();

    const int oc = tid >> 2;        // 0..63
    const int q  = tid & 3;         // spatial quadrant
    const int qy = q >> 1, qx = q & 1;
    const int y0a = qy * 4, x0a = qx * 4;   // conv1 4x4 block in 8x8
    const int y0b = qy * 3, x0b = qx * 3;   // conv2 3x3 block in 6x6

    float cur1[16], volt1[16];
#pragma unroll
    for (int i = 0; i < 16; ++i) { cur1[i] = 0.f; volt1[i] = 0.f; }

    const float* xin = input + (size_t)b * 20000;

    for (int t = 0; t < T_STEPS; ++t) {
        // ---- load input frame ----
        if (tid < 100) xs[tid] = xin[tid * 200 + t];
        __syncthreads();

        // ---- conv1: serial (ky,kx) FMA dot, bias after, unfused LIF ----
        {
            const float bb = b1s[oc];
#pragma unroll
            for (int iy = 0; iy < 4; ++iy) {
#pragma unroll
                for (int ix = 0; ix < 4; ++ix) {
                    const int y = y0a + iy, x = x0a + ix;
                    float a = 0.f;
#pragma unroll
                    for (int ky = 0; ky < 3; ++ky)
#pragma unroll
                        for (int kx = 0; kx < 3; ++kx)
                            a = __fmaf_rn(xs[(y + ky) * 10 + (x + kx)],
                                          w1s[oc * 9 + ky * 3 + kx], a);
                    const float psp = __fadd_rn(a, bb);
                    const int i = iy * 4 + ix;
                    const int sidx = oc * 65 + y * 8 + x;
                    float sp = s1s[sidx];
                    lif_update(psp, cur1[i], volt1[i], sp);
                    s1s[sidx] = sp;
                }
            }
        }
        __syncthreads();

        // ---- conv2: serial (ic, ky, kx) FMA dot per output, bias after ----
        {
            float acc[9];
#pragma unroll
            for (int i = 0; i < 9; ++i) acc[i] = 0.f;
            for (int ic = 0; ic < 64; ++ic) {
                float in[5][5];
#pragma unroll
                for (int r = 0; r < 5; ++r)
#pragma unroll
                    for (int c = 0; c < 5; ++c)
                        in[r][c] = s1s[ic * 65 + (y0b + r) * 8 + (x0b + c)];
#pragma unroll
                for (int kk = 0; kk < 9; ++kk) {
                    const int ky = kk / 3, kx = kk % 3;
                    const float w = w2s[(ic * 9 + kk) * 64 + oc];
#pragma unroll
                    for (int dy = 0; dy < 3; ++dy)
#pragma unroll
                        for (int dx = 0; dx < 3; ++dx)
                            acc[dy * 3 + dx] = __fmaf_rn(w, in[dy + ky][dx + kx],
                                                         acc[dy * 3 + dx]);
                }
            }
            const float bb = b2s[oc];
#pragma unroll
            for (int dy = 0; dy < 3; ++dy) {
#pragma unroll
                for (int dx = 0; dx < 3; ++dx) {
                    const int j = dy * 3 + dx;
                    const float psp = __fadd_rn(acc[j], bb);
                    const int idx = oc * 36 + (y0b + dy) * 6 + (x0b + dx);
                    float c = cur2[idx], v = volt2[idx], sp = s2s[idx];
                    lif_update(psp, c, v, sp);
                    cur2[idx] = c; volt2[idx] = v; s2s[idx] = sp;
                }
            }
        }
        __syncthreads();

        // ---- avgpool 2x2 -> write p[t][k][b] (exact: 0/1 spikes) ----
        for (int idx = tid; idx < 576; idx += 256) {
            int c = idx / 9;
            int pos = idx - c * 9;
            int py = pos / 3, px = pos - py * 3;
            float v = 0.25f * ((s2s[c * 36 + (2 * py) * 6 + 2 * px]
                              + s2s[c * 36 + (2 * py) * 6 + 2 * px + 1])
                             + (s2s[c * 36 + (2 * py + 1) * 6 + 2 * px]
                              + s2s[c * 36 + (2 * py + 1) * 6 + 2 * px + 1]));
            g_p[((size_t)t * 1152 + (size_t)(h * 64 + c) * 9 + pos) * 64 + b] = v;
        }
    }
}

// ============================================================================
// Phase B: conv3 -> LIF -> temporal conv -> LIF -> recurrent -> LIF -> fc1 ->
// LIF -> fc2 accumulate. grid = 64 CTAs (16 oc-groups x 4 b-groups), 256 thr.
// All dots: single serial accumulator over k with __fmaf_rn, bias after.
// ============================================================================
#define B_W3S   0        // 16*1160 = 18560
#define B_TCW   18560    // 3*16*264 = 12672
#define B_RECW  31232    // 16*264 = 4224
#define B_F1W   35456    // 16*264 = 4224
#define B_B3    39680    // 16
#define B_TCB   39696    // 48
#define B_RECB  39744    // 16
#define B_F1B   39760    // 16
#define B_F2S   39776    // 256
#define B_TOT   40032    // floats -> 160128 bytes

// serial FMA dot over k=256, activations strided by 64 floats
__device__ __forceinline__ float dot256s(const float* __restrict__ wr,
                                         const float* __restrict__ sc)
{
    float a = 0.f;
#pragma unroll
    for (int k = 0; k < 256; k += 4) {
        float4 w = *(const float4*)(wr + k);
        const float* p = sc + (size_t)k * 64;
        a = __fmaf_rn(w.x, p[0],   a);
        a = __fmaf_rn(w.y, p[64],  a);
        a = __fmaf_rn(w.z, p[128], a);
        a = __fmaf_rn(w.w, p[192], a);
    }
    return a;
}

__global__ __launch_bounds__(256, 1)
void phaseB_kernel(const float* __restrict__ w3, const float* __restrict__ b3,
                   const float* __restrict__ tcw, const float* __restrict__ tcb,
                   const float* __restrict__ recw, const float* __restrict__ recb,
                   const float* __restrict__ f1w, const float* __restrict__ f1b,
                   const float* __restrict__ f2w, const float* __restrict__ tsw,
                   float* __restrict__ out)
{
    extern __shared__ float sm[];
    float* w3s   = sm + B_W3S;
    float* tcws  = sm + B_TCW;
    float* recws = sm + B_RECW;
    float* f1ws  = sm + B_F1W;
    float* b3s   = sm + B_B3;
    float* tcbs  = sm + B_TCB;
    float* recbs = sm + B_RECB;
    float* f1bs  = sm + B_F1B;
    float* f2s   = sm + B_F2S;

    const int tid = threadIdx.x;
    const int og = blockIdx.x >> 2;   // 0..15
    const int bg = blockIdx.x & 3;    // 0..3
    const int ol = tid >> 4;          // 0..15
    const int bl = tid & 15;          // 0..15
    const int oc = og * 16 + ol;
    const int b  = bg * 16 + bl;

    // ---- one-time weight staging ----
    for (int g = tid; g < 16 * 1152; g += 256) {
        int o = g / 1152, k = g - o * 1152;
        w3s[o * 1160 + k] = w3[(size_t)(og * 16 + o) * 1152 + k];
    }
    for (int g = tid; g < 3 * 16 * 256; g += 256) {
        int i = g >> 12, r = g & 4095, o = r >> 8, k = r & 255;
        tcws[(i * 16 + o) * 264 + k] = tcw[i * 65536 + (og * 16 + o) * 256 + k];
    }
    for (int g = tid; g < 4096; g += 256) {
        int o = g >> 8, k = g & 255;
        recws[o * 264 + k] = recw[(og * 16 + o) * 256 + k];
        if (og < 8) f1ws[o * 264 + k] = f1w[(og * 16 + o) * 256 + k];
    }
    if (tid < 16) {
        b3s[tid] = b3[og * 16 + tid];
        recbs[tid] = recb[og * 16 + tid];
        if (og < 8) f1bs[tid] = f1b[og * 16 + tid];
    }
    if (tid < 48) tcbs[tid] = tcb[(tid >> 4) * 256 + og * 16 + (tid & 15)];
    f2s[tid] = f2w[tid];
    __syncthreads();

    float cur3 = 0.f, volt3 = 0.f, spk3 = 0.f;
    float curt = 0.f, voltt = 0.f, spkt = 0.f;
    float curr = 0.f, voltr = 0.f, spkr = 0.f;
    float curf = 0.f, voltf = 0.f, spkf = 0.f;
    float outacc = 0.f;

    for (int t = 0; t < T_STEPS; ++t) {
        // ---------- conv3: serial FMA dot over k=1152, bias after ----------
        {
            const float* pc = g_p + (size_t)t * 1152 * 64 + b;
            const float* wr = w3s + ol * 1160;
            float a = 0.f;
#pragma unroll 8
            for (int k = 0; k < 1152; k += 4) {
                float4 w = *(const float4*)(wr + k);
                const float* pp = pc + (size_t)k * 64;
                a = __fmaf_rn(w.x, pp[0],   a);
                a = __fmaf_rn(w.y, pp[64],  a);
                a = __fmaf_rn(w.z, pp[128], a);
                a = __fmaf_rn(w.w, pp[192], a);
            }
            const float psp = __fadd_rn(a, b3s[ol]);
            lif_update(psp, cur3, volt3, spk3);
            g_s3[(t % 3) * 16384 + oc * 64 + b] = spk3;
        }
        gridbar(64);

        // ---------- temporal conv + LIF, fused with recurrent + LIF ----------
        {
            // psp = ((tap0) + tap1) + tap2, tap_i = dot_i + bias_i
            float a = 0.f;
#pragma unroll
            for (int i = 0; i < 3; ++i) {
                if (t >= i) {
                    const int slot = (t - i) % 3;
                    const float d = dot256s(tcws + (i * 16 + ol) * 264,
                                            g_s3 + slot * 16384 + b);
                    const float tap = __fadd_rn(d, tcbs[i * 16 + ol]);
                    a = __fadd_rn(a, tap);
                }
            }
            lif_update(a, curt, voltt, spkt);

            // recurrent: psp = (s_tc + dot) + bias
            float dotr = 0.f;
            if (t > 0)
                dotr = dot256s(recws + ol * 264, g_sr + ((t & 1) ^ 1) * 16384 + b);
            const float pr = __fadd_rn(__fadd_rn(spkt, dotr), recbs[ol]);
            lif_update(pr, curr, voltr, spkr);
            g_sr[(t & 1) * 16384 + oc * 64 + b] = spkr;
        }
        gridbar(64);

        // ---------- fc1 + LIF (og < 8 covers all 128 neurons) ----------
        if (og < 8) {
            const float d = dot256s(f1ws + ol * 264, g_sr + (t & 1) * 16384 + b);
            const float psp = __fadd_rn(d, f1bs[ol]);
            lif_update(psp, curf, voltf, spkf);
            g_sf[oc * 64 + b] = spkf;
        }
        gridbar(64);

        // ---------- fc2 + timestep weighting (og==0, 2 outputs x 16 b) ----------
        if (og == 0 && ol < 2) {
            const float* sc = g_sf + b;
            const float* wr = f2s + ol * 128;
            float d = 0.f;
#pragma unroll
            for (int k = 0; k < 128; k += 4) {
                float4 w = *(const float4*)(wr + k);
                const float* p = sc + (size_t)k * 64;
                d = __fmaf_rn(w.x, p[0],   d);
                d = __fmaf_rn(w.y, p[64],  d);
                d = __fmaf_rn(w.z, p[128], d);
                d = __fmaf_rn(w.w, p[192], d);
            }
            outacc = __fadd_rn(outacc, __fmul_rn(d, tsw[t]));
        }
    }

    if (og == 0 && ol < 2) out[b * 2 + ol] = outacc;
}

// ============================================================================
extern "C" void kernel_launch(void* const* d_in, const int* in_sizes, int n_in,
                              void* d_out, int out_size)
{
    (void)in_sizes; (void)n_in; (void)out_size;
    const float* input = (const float*)d_in[0];
    const float* w1   = (const float*)d_in[1];
    const float* b1   = (const float*)d_in[2];
    const float* w2   = (const float*)d_in[3];
    const float* b2   = (const float*)d_in[4];
    const float* w3   = (const float*)d_in[5];
    const float* b3   = (const float*)d_in[6];
    const float* tcw  = (const float*)d_in[7];
    const float* tcb  = (const float*)d_in[8];
    const float* recw = (const float*)d_in[9];
    const float* recb = (const float*)d_in[10];
    const float* f1w  = (const float*)d_in[11];
    const float* f1b  = (const float*)d_in[12];
    const float* f2w  = (const float*)d_in[13];
    const float* tsw  = (const float*)d_in[14];
    float* out = (float*)d_out;

    cudaFuncSetAttribute(phaseA_kernel, cudaFuncAttributeMaxDynamicSharedMemorySize,
                         A_TOT * sizeof(float));
    cudaFuncSetAttribute(phaseB_kernel, cudaFuncAttributeMaxDynamicSharedMemorySize,
                         B_TOT * sizeof(float));

    phaseA_kernel<<<128, 256, A_TOT * sizeof(float)>>>(input, w1, b1, w2, b2);
    phaseB_kernel<<<64, 256, B_TOT * sizeof(float)>>>(w3, b3, tcw, tcb, recw, recb,
                                                      f1w, f1b, f2w, tsw, out);
}

// round 4
// speedup vs baseline: 1.0457x; 1.0457x over previous
#include <cuda_runtime.h>
#include <cstdint>

#define T_STEPS 200

typedef unsigned long long u64t;

// ---------------- scratch (device globals: allocation-free) ----------------
// g_p layout: [t][k/4][b][4]  (k = (h*64+c)*9+pos, 1152 total; 288 k4-groups)
__device__ float g_p[(size_t)T_STEPS * 288 * 64 * 4];   // ~59MB
// g_s3 layout: [slot][k/4][b][4], k = oc (256)
__device__ float g_s3[3 * 64 * 64 * 4];
// g_sr layout: [buf][k/4][b][4], k = oc (256)
__device__ float g_sr[2 * 64 * 64 * 4];
// g_sf layout: [k/4][b][4], k = oc (128)
__device__ float g_sf[32 * 64 * 4];
__device__ unsigned g_cnt = 0;
__device__ volatile unsigned g_gen = 0;

__device__ __forceinline__ void gridbar(unsigned n) {
    __syncthreads();
    if (threadIdx.x == 0) {
        unsigned gen = g_gen;
        __threadfence();
        if (atomicAdd(&g_cnt, 1u) == n - 1u) {
            g_cnt = 0;
            __threadfence();
            g_gen = gen + 1u;
        } else {
            while (g_gen == gen) { }
        }
        __threadfence();
    }
    __syncthreads();
}

// ---- packed f32x2 helpers (each lane = independent rn op: bit-exact) ----
__device__ __forceinline__ u64t pk2(float lo, float hi) {
    u64t r; asm("mov.b64 %0, {%1, %2};" : "=l"(r) : "f"(lo), "f"(hi)); return r;
}
__device__ __forceinline__ void upk2(u64t v, float& lo, float& hi) {
    asm("mov.b64 {%0, %1}, %2;" : "=f"(lo), "=f"(hi) : "l"(v));
}
__device__ __forceinline__ u64t fma2(u64t a, u64t b, u64t c) {
    u64t d; asm("fma.rn.f32x2 %0, %1, %2, %3;" : "=l"(d) : "l"(a), "l"(b), "l"(c));
    return d;
}

// LIF update, unfused rounding (XLA elementwise semantics) — unchanged from R3
__device__ __forceinline__ void lif_update(float psp, float& cur, float& volt, float& spk) {
    cur  = __fadd_rn(__fmul_rn(0.5f, cur), psp);
    volt = __fadd_rn(__fmul_rn(__fmul_rn(0.75f, volt), __fadd_rn(1.f, -spk)), cur);
    spk  = (volt > 0.5f) ? 1.f : 0.f;
}

// ============================================================================
// Phase A: conv1 -> LIF -> conv2 (FFMA2 oc-pairs) -> LIF -> avgpool.
// grid = 128 CTAs (2 per batch: h = conv2 oc-half), 128 threads.
// thread = (oc-pair p 0..31, quadrant q 0..3)
// ============================================================================
#define A_XS    0        // 100
#define A_W1S   100      // 576  (scalar [oc*9+k])
#define A_B1S   676      // 64
#define A_B2S   740      // 64
#define A_S1S   804      // 64*65 = 4160
#define A_S2S   4964     // 2304
#define A_W2P   7268     // 576*64 = 36864, layout [(r*32+p)*2 + (oc&1)]
#define A_TOT   44132    // floats -> 176528 bytes

__global__ __launch_bounds__(128, 1)
void phaseA_kernel(const float* __restrict__ input,
                   const float* __restrict__ w1, const float* __restrict__ b1,
                   const float* __restrict__ w2, const float* __restrict__ b2)
{
    extern __shared__ float sm[];
    float* xs  = sm + A_XS;
    float* w1s = sm + A_W1S;
    float* b1s = sm + A_B1S;
    float* b2s = sm + A_B2S;
    float* s1s = sm + A_S1S;
    float* s2s = sm + A_S2S;
    float* w2p = sm + A_W2P;

    const int tid = threadIdx.x;
    const int b   = blockIdx.x >> 1;
    const int h   = blockIdx.x & 1;

    // ---- one-time staging ----
    // conv2 half-weights interleaved by oc-pair: w2p[(r*32+p)*2 + (oc&1)]
    for (int i = tid; i < 36864; i += 128) {
        int oc = i / 576;
        int r  = i - oc * 576;
        w2p[(r * 32 + (oc >> 1)) * 2 + (oc & 1)] = w2[h * 36864 + i];
    }
    for (int i = tid; i < 576; i += 128) w1s[i] = w1[i];
    if (tid < 64) { b1s[tid] = b1[tid]; b2s[tid] = b2[h * 64 + tid]; }
    for (int i = tid; i < 4160; i += 128) s1s[i] = 0.f;
    for (int i = tid; i < 2304; i += 128) s2s[i] = 0.f;
    __syncthreads();

    const int p = tid >> 2;         // oc pair index 0..31
    const int q = tid & 3;
    const int qy = q >> 1, qx = q & 1;
    const int y0a = qy * 4, x0a = qx * 4;   // conv1 4x4 block in 8x8
    const int y0b = qy * 3, x0b = qx * 3;   // conv2 3x3 block in 6x6

    float c1[2][16], v1[2][16];
    float c2[2][9], v2[2][9], sp2[2][9];
#pragma unroll
    for (int o = 0; o < 2; ++o) {
#pragma unroll
        for (int i = 0; i < 16; ++i) { c1[o][i] = 0.f; v1[o][i] = 0.f; }
#pragma unroll
        for (int i = 0; i < 9; ++i) { c2[o][i] = 0.f; v2[o][i] = 0.f; sp2[o][i] = 0.f; }
    }

    const float* xin = input + (size_t)b * 20000;

    for (int t = 0; t < T_STEPS; ++t) {
        // ---- load input frame ----
        if (tid < 100) xs[tid] = xin[tid * 200 + t];
        __syncthreads();

        // ---- conv1: serial scalar FMA per oc (2 ocs), identical to R3 ----
#pragma unroll
        for (int o = 0; o < 2; ++o) {
            const int occ = 2 * p + o;
            const float bb = b1s[occ];
            const float* wv = w1s + occ * 9;
#pragma unroll
            for (int iy = 0; iy < 4; ++iy) {
#pragma unroll
                for (int ix = 0; ix < 4; ++ix) {
                    const int y = y0a + iy, x = x0a + ix;
                    float a = 0.f;
#pragma unroll
                    for (int ky = 0; ky < 3; ++ky)
#pragma unroll
                        for (int kx = 0; kx < 3; ++kx)
                            a = __fmaf_rn(xs[(y + ky) * 10 + (x + kx)], wv[ky * 3 + kx], a);
                    const float psp = __fadd_rn(a, bb);
                    const int i = iy * 4 + ix;
                    const int sidx = occ * 65 + y * 8 + x;
                    float sp = s1s[sidx];
                    lif_update(psp, c1[o][i], v1[o][i], sp);
                    s1s[sidx] = sp;
                }
            }
        }
        __syncthreads();

        // ---- conv2: packed FFMA2 across oc-pair, serial (ic,ky,kx) per oc ----
        {
            u64t acc[9];
#pragma unroll
            for (int j = 0; j < 9; ++j) acc[j] = 0ull;   // (0.f, 0.f)

#pragma unroll 2
            for (int ic = 0; ic < 64; ++ic) {
                u64t ins[5][5];
#pragma unroll
                for (int r = 0; r < 5; ++r)
#pragma unroll
                    for (int c = 0; c < 5; ++c) {
                        float v = s1s[ic * 65 + (y0b + r) * 8 + (x0b + c)];
                        ins[r][c] = pk2(v, v);
                    }
#pragma unroll
                for (int kk = 0; kk < 9; ++kk) {
                    const int ky = kk / 3, kx = kk % 3;
                    const u64t w = *(const u64t*)(w2p + ((ic * 9 + kk) * 32 + p) * 2);
#pragma unroll
                    for (int dy = 0; dy < 3; ++dy)
#pragma unroll
                        for (int dx = 0; dx < 3; ++dx)
                            acc[dy * 3 + dx] = fma2(ins[dy + ky][dx + kx], w,
                                                    acc[dy * 3 + dx]);
                }
            }

            // LIF scalar per oc (unchanged rounding path)
#pragma unroll
            for (int j = 0; j < 9; ++j) {
                const int dy = j / 3, dx = j % 3;
                float alo, ahi;
                upk2(acc[j], alo, ahi);
#pragma unroll
                for (int o = 0; o < 2; ++o) {
                    const int occ = 2 * p + o;
                    const float a = o ? ahi : alo;
                    const float psp = __fadd_rn(a, b2s[occ]);
                    lif_update(psp, c2[o][j], v2[o][j], sp2[o][j]);
                    s2s[occ * 36 + (y0b + dy) * 6 + (x0b + dx)] = sp2[o][j];
                }
            }
        }
        __syncthreads();

        // ---- avgpool 2x2 -> g_p[t][k/4][b][4] ----
        for (int idx = tid; idx < 576; idx += 128) {
            int c = idx / 9;
            int pos = idx - c * 9;
            int py = pos / 3, px = pos - py * 3;
            float v = 0.25f * ((s2s[c * 36 + (2 * py) * 6 + 2 * px]
                              + s2s[c * 36 + (2 * py) * 6 + 2 * px + 1])
                             + (s2s[c * 36 + (2 * py + 1) * 6 + 2 * px]
                              + s2s[c * 36 + (2 * py + 1) * 6 + 2 * px + 1]));
            int k = (h * 64 + c) * 9 + pos;
            g_p[(size_t)t * 73728 + (size_t)(k >> 2) * 256 + b * 4 + (k & 3)] = v;
        }
    }
}

// ============================================================================
// Phase B: conv3 -> LIF -> tc -> LIF -> rec -> LIF -> fc1 -> LIF -> fc2.
// grid = 64 CTAs (16 og x 4 bg), 256 threads, thread = (ol 0..15, bl 0..15).
// Serial FMA chains, float4 activation loads from [k/4][b][4] layouts.
// ============================================================================
#define B_W3S   0        // 16*1160 = 18560
#define B_TCW   18560    // 3*16*264 = 12672
#define B_RECW  31232    // 16*264 = 4224
#define B_F1W   35456    // 16*264 = 4224
#define B_B3    39680    // 16
#define B_TCB   39696    // 48
#define B_RECB  39744    // 16
#define B_F1B   39760    // 16
#define B_F2S   39776    // 256
#define B_TOT   40032    // floats -> 160128 bytes

// serial FMA dot over k=256; act base sc = array + b*4 (layout [k4][b][4])
__device__ __forceinline__ float dot256v(const float* __restrict__ wr,
                                         const float* __restrict__ sc)
{
    float a = 0.f;
#pragma unroll 8
    for (int k4 = 0; k4 < 64; ++k4) {
        float4 w = *(const float4*)(wr + k4 * 4);
        float4 x = *(const float4*)(sc + k4 * 256);
        a = __fmaf_rn(w.x, x.x, a);
        a = __fmaf_rn(w.y, x.y, a);
        a = __fmaf_rn(w.z, x.z, a);
        a = __fmaf_rn(w.w, x.w, a);
    }
    return a;
}

__global__ __launch_bounds__(256, 1)
void phaseB_kernel(const float* __restrict__ w3, const float* __restrict__ b3,
                   const float* __restrict__ tcw, const float* __restrict__ tcb,
                   const float* __restrict__ recw, const float* __restrict__ recb,
                   const float* __restrict__ f1w, const float* __restrict__ f1b,
                   const float* __restrict__ f2w, const float* __restrict__ tsw,
                   float* __restrict__ out)
{
    extern __shared__ float sm[];
    float* w3s   = sm + B_W3S;
    float* tcws  = sm + B_TCW;
    float* recws = sm + B_RECW;
    float* f1ws  = sm + B_F1W;
    float* b3s   = sm + B_B3;
    float* tcbs  = sm + B_TCB;
    float* recbs = sm + B_RECB;
    float* f1bs  = sm + B_F1B;
    float* f2s   = sm + B_F2S;

    const int tid = threadIdx.x;
    const int og = blockIdx.x >> 2;   // 0..15
    const int bg = blockIdx.x & 3;    // 0..3
    const int ol = tid >> 4;          // 0..15
    const int bl = tid & 15;          // 0..15
    const int oc = og * 16 + ol;
    const int b  = bg * 16 + bl;

    // ---- one-time weight staging ----
    for (int g = tid; g < 16 * 1152; g += 256) {
        int o = g / 1152, k = g - o * 1152;
        w3s[o * 1160 + k] = w3[(size_t)(og * 16 + o) * 1152 + k];
    }
    for (int g = tid; g < 3 * 16 * 256; g += 256) {
        int i = g >> 12, r = g & 4095, o = r >> 8, k = r & 255;
        tcws[(i * 16 + o) * 264 + k] = tcw[i * 65536 + (og * 16 + o) * 256 + k];
    }
    for (int g = tid; g < 4096; g += 256) {
        int o = g >> 8, k = g & 255;
        recws[o * 264 + k] = recw[(og * 16 + o) * 256 + k];
        if (og < 8) f1ws[o * 264 + k] = f1w[(og * 16 + o) * 256 + k];
    }
    if (tid < 16) {
        b3s[tid] = b3[og * 16 + tid];
        recbs[tid] = recb[og * 16 + tid];
        if (og < 8) f1bs[tid] = f1b[og * 16 + tid];
    }
    if (tid < 48) tcbs[tid] = tcb[(tid >> 4) * 256 + og * 16 + (tid & 15)];
    f2s[tid] = f2w[tid];
    __syncthreads();

    float cur3 = 0.f, volt3 = 0.f, spk3 = 0.f;
    float curt = 0.f, voltt = 0.f, spkt = 0.f;
    float curr = 0.f, voltr = 0.f, spkr = 0.f;
    float curf = 0.f, voltf = 0.f, spkf = 0.f;
    float outacc = 0.f;

    for (int t = 0; t < T_STEPS; ++t) {
        // ---------- conv3: serial FMA dot over k=1152, float4 loads ----------
        {
            const float* pc = g_p + (size_t)t * 73728 + b * 4;
            const float* wr = w3s + ol * 1160;
            float a = 0.f;
#pragma unroll 8
            for (int k4 = 0; k4 < 288; ++k4) {
                float4 w = *(const float4*)(wr + k4 * 4);
                float4 x = *(const float4*)(pc + (size_t)k4 * 256);
                a = __fmaf_rn(w.x, x.x, a);
                a = __fmaf_rn(w.y, x.y, a);
                a = __fmaf_rn(w.z, x.z, a);
                a = __fmaf_rn(w.w, x.w, a);
            }
            const float psp = __fadd_rn(a, b3s[ol]);
            lif_update(psp, cur3, volt3, spk3);
            g_s3[((t % 3) * 64 + (oc >> 2)) * 256 + b * 4 + (oc & 3)] = spk3;
        }
        gridbar(64);

        // ---------- temporal conv + LIF, fused with recurrent + LIF ----------
        {
            float a = 0.f;
#pragma unroll
            for (int i = 0; i < 3; ++i) {
                if (t >= i) {
                    const int slot = (t - i) % 3;
                    const float d = dot256v(tcws + (i * 16 + ol) * 264,
                                            g_s3 + slot * 16384 + b * 4);
                    const float tap = __fadd_rn(d, tcbs[i * 16 + ol]);
                    a = __fadd_rn(a, tap);
                }
            }
            lif_update(a, curt, voltt, spkt);

            // recurrent: psp = (s_tc + dot) + bias
            float dotr = 0.f;
            if (t > 0)
                dotr = dot256v(recws + ol * 264, g_sr + ((t & 1) ^ 1) * 16384 + b * 4);
            const float pr = __fadd_rn(__fadd_rn(spkt, dotr), recbs[ol]);
            lif_update(pr, curr, voltr, spkr);
            g_sr[((t & 1) * 64 + (oc >> 2)) * 256 + b * 4 + (oc & 3)] = spkr;
        }
        gridbar(64);

        // ---------- fc1 + LIF (og < 8 covers all 128 neurons) ----------
        if (og < 8) {
            const float d = dot256v(f1ws + ol * 264, g_sr + (t & 1) * 16384 + b * 4);
            const float psp = __fadd_rn(d, f1bs[ol]);
            lif_update(psp, curf, voltf, spkf);
            g_sf[(oc >> 2) * 256 + b * 4 + (oc & 3)] = spkf;
        }
        gridbar(64);

        // ---------- fc2 + timestep weighting (og==0, 2 outputs x 16 b) ----------
        if (og == 0 && ol < 2) {
            const float* sc = g_sf + b * 4;
            const float* wr = f2s + ol * 128;
            float d = 0.f;
#pragma unroll 8
            for (int k4 = 0; k4 < 32; ++k4) {
                float4 w = *(const float4*)(wr + k4 * 4);
                float4 x = *(const float4*)(sc + k4 * 256);
                d = __fmaf_rn(w.x, x.x, d);
                d = __fmaf_rn(w.y, x.y, d);
                d = __fmaf_rn(w.z, x.z, d);
                d = __fmaf_rn(w.w, x.w, d);
            }
            outacc = __fadd_rn(outacc, __fmul_rn(d, tsw[t]));
        }
    }

    if (og == 0 && ol < 2) out[b * 2 + ol] = outacc;
}

// ============================================================================
extern "C" void kernel_launch(void* const* d_in, const int* in_sizes, int n_in,
                              void* d_out, int out_size)
{
    (void)in_sizes; (void)n_in; (void)out_size;
    const float* input = (const float*)d_in[0];
    const float* w1   = (const float*)d_in[1];
    const float* b1   = (const float*)d_in[2];
    const float* w2   = (const float*)d_in[3];
    const float* b2   = (const float*)d_in[4];
    const float* w3   = (const float*)d_in[5];
    const float* b3   = (const float*)d_in[6];
    const float* tcw  = (const float*)d_in[7];
    const float* tcb  = (const float*)d_in[8];
    const float* recw = (const float*)d_in[9];
    const float* recb = (const float*)d_in[10];
    const float* f1w  = (const float*)d_in[11];
    const float* f1b  = (const float*)d_in[12];
    const float* f2w  = (const float*)d_in[13];
    const float* tsw  = (const float*)d_in[14];
    float* out = (float*)d_out;

    cudaFuncSetAttribute(phaseA_kernel, cudaFuncAttributeMaxDynamicSharedMemorySize,
                         A_TOT * sizeof(float));
    cudaFuncSetAttribute(phaseB_kernel, cudaFuncAttributeMaxDynamicSharedMemorySize,
                         B_TOT * sizeof(float));

    phaseA_kernel<<<128, 128, A_TOT * sizeof(float)>>>(input, w1, b1, w2, b2);
    phaseB_kernel<<<64, 256, B_TOT * sizeof(float)>>>(w3, b3, tcw, tcb, recw, recb,
                                                      f1w, f1b, f2w, tsw, out);
}

// round 5
// speedup vs baseline: 1.5221x; 1.4556x over previous
#include <cuda_runtime.h>
#include <cstdint>

#define T_STEPS 200

typedef unsigned long long u64t;

// ---------------- scratch (device globals: allocation-free) ----------------
// g_p layout: [t][k/4][b][4]  (k = (h*64+c)*9+pos, 1152 total; 288 k4-groups)
__device__ float g_p[(size_t)T_STEPS * 288 * 64 * 4];   // ~59MB
// g_s3 layout: [slot][k/4][b][4], k = oc (256)
__device__ float g_s3[3 * 64 * 64 * 4];
// g_sr layout: [buf][k/4][b][4], k = oc (256)
__device__ float g_sr[2 * 64 * 64 * 4];
// g_sf layout: [k/4][b][4], k = oc (128)
__device__ float g_sf[32 * 64 * 4];
// per-bg-group barriers (padded to separate cache lines)
__device__ unsigned g_cnt[4 * 32];
__device__ volatile unsigned g_gen[4 * 32];

__device__ __forceinline__ void gridbar_g(int grp, unsigned n) {
    __syncthreads();
    if (threadIdx.x == 0) {
        unsigned* cnt = &g_cnt[grp * 32];
        volatile unsigned* gen = &g_gen[grp * 32];
        unsigned g = *gen;
        __threadfence();
        if (atomicAdd(cnt, 1u) == n - 1u) {
            *cnt = 0;
            __threadfence();
            *gen = g + 1u;
        } else {
            while (*gen == g) { }
        }
        __threadfence();
    }
    __syncthreads();
}

// ---- packed f32x2 helpers (each lane = independent rn op: bit-exact) ----
__device__ __forceinline__ u64t pk2(float lo, float hi) {
    u64t r; asm("mov.b64 %0, {%1, %2};" : "=l"(r) : "f"(lo), "f"(hi)); return r;
}
__device__ __forceinline__ void upk2(u64t v, float& lo, float& hi) {
    asm("mov.b64 {%0, %1}, %2;" : "=f"(lo), "=f"(hi) : "l"(v));
}
__device__ __forceinline__ u64t fma2(u64t a, u64t b, u64t c) {
    u64t d; asm("fma.rn.f32x2 %0, %1, %2, %3;" : "=l"(d) : "l"(a), "l"(b), "l"(c));
    return d;
}

// LIF update, unfused rounding (XLA elementwise semantics)
__device__ __forceinline__ void lif_update(float psp, float& cur, float& volt, float& spk) {
    cur  = __fadd_rn(__fmul_rn(0.5f, cur), psp);
    volt = __fadd_rn(__fmul_rn(__fmul_rn(0.75f, volt), __fadd_rn(1.f, -spk)), cur);
    spk  = (volt > 0.5f) ? 1.f : 0.f;
}

// ============================================================================
// Phase A: conv1 -> LIF -> conv2 (FFMA2 oc-pairs) -> LIF -> avgpool.
// grid = 128 CTAs (2 per batch: h = conv2 oc-half), 128 threads.  (unchanged R4)
// ============================================================================
#define A_XS    0
#define A_W1S   100
#define A_B1S   676
#define A_B2S   740
#define A_S1S   804
#define A_S2S   4964
#define A_W2P   7268
#define A_TOT   44132

__global__ __launch_bounds__(128, 1)
void phaseA_kernel(const float* __restrict__ input,
                   const float* __restrict__ w1, const float* __restrict__ b1,
                   const float* __restrict__ w2, const float* __restrict__ b2)
{
    extern __shared__ float sm[];
    float* xs  = sm + A_XS;
    float* w1s = sm + A_W1S;
    float* b1s = sm + A_B1S;
    float* b2s = sm + A_B2S;
    float* s1s = sm + A_S1S;
    float* s2s = sm + A_S2S;
    float* w2p = sm + A_W2P;

    const int tid = threadIdx.x;
    const int b   = blockIdx.x >> 1;
    const int h   = blockIdx.x & 1;

    for (int i = tid; i < 36864; i += 128) {
        int oc = i / 576;
        int r  = i - oc * 576;
        w2p[(r * 32 + (oc >> 1)) * 2 + (oc & 1)] = w2[h * 36864 + i];
    }
    for (int i = tid; i < 576; i += 128) w1s[i] = w1[i];
    if (tid < 64) { b1s[tid] = b1[tid]; b2s[tid] = b2[h * 64 + tid]; }
    for (int i = tid; i < 4160; i += 128) s1s[i] = 0.f;
    for (int i = tid; i < 2304; i += 128) s2s[i] = 0.f;
    __syncthreads();

    const int p = tid >> 2;
    const int q = tid & 3;
    const int qy = q >> 1, qx = q & 1;
    const int y0a = qy * 4, x0a = qx * 4;
    const int y0b = qy * 3, x0b = qx * 3;

    float c1[2][16], v1[2][16];
    float c2[2][9], v2[2][9], sp2[2][9];
#pragma unroll
    for (int o = 0; o < 2; ++o) {
#pragma unroll
        for (int i = 0; i < 16; ++i) { c1[o][i] = 0.f; v1[o][i] = 0.f; }
#pragma unroll
        for (int i = 0; i < 9; ++i) { c2[o][i] = 0.f; v2[o][i] = 0.f; sp2[o][i] = 0.f; }
    }

    const float* xin = input + (size_t)b * 20000;

    for (int t = 0; t < T_STEPS; ++t) {
        if (tid < 100) xs[tid] = xin[tid * 200 + t];
        __syncthreads();

#pragma unroll
        for (int o = 0; o < 2; ++o) {
            const int occ = 2 * p + o;
            const float bb = b1s[occ];
            const float* wv = w1s + occ * 9;
#pragma unroll
            for (int iy = 0; iy < 4; ++iy) {
#pragma unroll
                for (int ix = 0; ix < 4; ++ix) {
                    const int y = y0a + iy, x = x0a + ix;
                    float a = 0.f;
#pragma unroll
                    for (int ky = 0; ky < 3; ++ky)
#pragma unroll
                        for (int kx = 0; kx < 3; ++kx)
                            a = __fmaf_rn(xs[(y + ky) * 10 + (x + kx)], wv[ky * 3 + kx], a);
                    const float psp = __fadd_rn(a, bb);
                    const int i = iy * 4 + ix;
                    const int sidx = occ * 65 + y * 8 + x;
                    float sp = s1s[sidx];
                    lif_update(psp, c1[o][i], v1[o][i], sp);
                    s1s[sidx] = sp;
                }
            }
        }
        __syncthreads();

        {
            u64t acc[9];
#pragma unroll
            for (int j = 0; j < 9; ++j) acc[j] = 0ull;

#pragma unroll 2
            for (int ic = 0; ic < 64; ++ic) {
                u64t ins[5][5];
#pragma unroll
                for (int r = 0; r < 5; ++r)
#pragma unroll
                    for (int c = 0; c < 5; ++c) {
                        float v = s1s[ic * 65 + (y0b + r) * 8 + (x0b + c)];
                        ins[r][c] = pk2(v, v);
                    }
#pragma unroll
                for (int kk = 0; kk < 9; ++kk) {
                    const int ky = kk / 3, kx = kk % 3;
                    const u64t w = *(const u64t*)(w2p + ((ic * 9 + kk) * 32 + p) * 2);
#pragma unroll
                    for (int dy = 0; dy < 3; ++dy)
#pragma unroll
                        for (int dx = 0; dx < 3; ++dx)
                            acc[dy * 3 + dx] = fma2(ins[dy + ky][dx + kx], w,
                                                    acc[dy * 3 + dx]);
                }
            }

#pragma unroll
            for (int j = 0; j < 9; ++j) {
                const int dy = j / 3, dx = j % 3;
                float alo, ahi;
                upk2(acc[j], alo, ahi);
#pragma unroll
                for (int o = 0; o < 2; ++o) {
                    const int occ = 2 * p + o;
                    const float a = o ? ahi : alo;
                    const float psp = __fadd_rn(a, b2s[occ]);
                    lif_update(psp, c2[o][j], v2[o][j], sp2[o][j]);
                    s2s[occ * 36 + (y0b + dy) * 6 + (x0b + dx)] = sp2[o][j];
                }
            }
        }
        __syncthreads();

        for (int idx = tid; idx < 576; idx += 128) {
            int c = idx / 9;
            int pos = idx - c * 9;
            int py = pos / 3, px = pos - py * 3;
            float v = 0.25f * ((s2s[c * 36 + (2 * py) * 6 + 2 * px]
                              + s2s[c * 36 + (2 * py) * 6 + 2 * px + 1])
                             + (s2s[c * 36 + (2 * py + 1) * 6 + 2 * px]
                              + s2s[c * 36 + (2 * py + 1) * 6 + 2 * px + 1]));
            int k = (h * 64 + c) * 9 + pos;
            g_p[(size_t)t * 73728 + (size_t)(k >> 2) * 256 + b * 4 + (k & 3)] = v;
        }
    }
}

// ============================================================================
// Phase B: latency-decoupled. grid = 64 CTAs (16 og x 4 bg), 256 threads.
// conv3: SMEM double-buffered staging of g_p chunks.
// tc: rolling 3-slot SMEM cache of s3 spikes.
// rec/fc1/fc2: register ping-pong prefetch from L2.
// Per-bg-group barriers (4 independent groups of 16 CTAs).
// ============================================================================
#define B_W3S   0        // 16*1160 = 18560
#define B_TCW   18560    // 12672
#define B_RECW  31232    // 4224
#define B_F1W   35456    // 4224
#define B_B3    39680    // 16
#define B_TCB   39696    // 48
#define B_RECB  39744    // 16
#define B_F1B   39760    // 16
#define B_F2S   39776    // 256
#define B_S3C   40032    // 3*4096 = 12288 (rolling s3 cache [slot][k4][bl][4])
#define B_PBUF  52320    // 2*2048 = 4096 (conv3 chunk double buffer)
#define B_TOT   56416    // floats -> 225664 bytes

// serial FMA dot over k=256 with register ping-pong prefetch (groups of 8 k4)
__device__ __forceinline__ float dot256pf(const float* __restrict__ wr,
                                          const float* __restrict__ sc)
{
    float4 x[16];
#pragma unroll
    for (int j = 0; j < 8; ++j) x[j] = *(const float4*)(sc + j * 256);
    float a = 0.f;
#pragma unroll
    for (int g = 0; g < 8; ++g) {
        const int cb = (g & 1) * 8;
        const int nb = ((g + 1) & 1) * 8;
        if (g < 7) {
#pragma unroll
            for (int j = 0; j < 8; ++j)
                x[nb + j] = *(const float4*)(sc + ((g + 1) * 8 + j) * 256);
        }
#pragma unroll
        for (int j = 0; j < 8; ++j) {
            float4 w = *(const float4*)(wr + (g * 8 + j) * 4);
            a = __fmaf_rn(w.x, x[cb + j].x, a);
            a = __fmaf_rn(w.y, x[cb + j].y, a);
            a = __fmaf_rn(w.z, x[cb + j].z, a);
            a = __fmaf_rn(w.w, x[cb + j].w, a);
        }
    }
    return a;
}

// serial FMA dot over k=128 with register prefetch (4 groups of 8 k4)
__device__ __forceinline__ float dot128pf(const float* __restrict__ wr,
                                          const float* __restrict__ sc)
{
    float4 x[16];
#pragma unroll
    for (int j = 0; j < 8; ++j) x[j] = *(const float4*)(sc + j * 256);
    float a = 0.f;
#pragma unroll
    for (int g = 0; g < 4; ++g) {
        const int cb = (g & 1) * 8;
        const int nb = ((g + 1) & 1) * 8;
        if (g < 3) {
#pragma unroll
            for (int j = 0; j < 8; ++j)
                x[nb + j] = *(const float4*)(sc + ((g + 1) * 8 + j) * 256);
        }
#pragma unroll
        for (int j = 0; j < 8; ++j) {
            float4 w = *(const float4*)(wr + (g * 8 + j) * 4);
            a = __fmaf_rn(w.x, x[cb + j].x, a);
            a = __fmaf_rn(w.y, x[cb + j].y, a);
            a = __fmaf_rn(w.z, x[cb + j].z, a);
            a = __fmaf_rn(w.w, x[cb + j].w, a);
        }
    }
    return a;
}

__global__ __launch_bounds__(256, 1)
void phaseB_kernel(const float* __restrict__ w3, const float* __restrict__ b3,
                   const float* __restrict__ tcw, const float* __restrict__ tcb,
                   const float* __restrict__ recw, const float* __restrict__ recb,
                   const float* __restrict__ f1w, const float* __restrict__ f1b,
                   const float* __restrict__ f2w, const float* __restrict__ tsw,
                   float* __restrict__ out)
{
    extern __shared__ float sm[];
    float* w3s   = sm + B_W3S;
    float* tcws  = sm + B_TCW;
    float* recws = sm + B_RECW;
    float* f1ws  = sm + B_F1W;
    float* b3s   = sm + B_B3;
    float* tcbs  = sm + B_TCB;
    float* recbs = sm + B_RECB;
    float* f1bs  = sm + B_F1B;
    float* f2s   = sm + B_F2S;
    float* s3c   = sm + B_S3C;
    float* pb0   = sm + B_PBUF;
    float* pb1   = sm + B_PBUF + 2048;

    const int tid = threadIdx.x;
    const int og = blockIdx.x >> 2;   // 0..15
    const int bg = blockIdx.x & 3;    // 0..3 (independent barrier group)
    const int ol = tid >> 4;          // 0..15
    const int bl = tid & 15;          // 0..15
    const int oc = og * 16 + ol;
    const int b  = bg * 16 + bl;

    // ---- one-time weight staging ----
    for (int g = tid; g < 16 * 1152; g += 256) {
        int o = g / 1152, k = g - o * 1152;
        w3s[o * 1160 + k] = w3[(size_t)(og * 16 + o) * 1152 + k];
    }
    for (int g = tid; g < 3 * 16 * 256; g += 256) {
        int i = g >> 12, r = g & 4095, o = r >> 8, k = r & 255;
        tcws[(i * 16 + o) * 264 + k] = tcw[i * 65536 + (og * 16 + o) * 256 + k];
    }
    for (int g = tid; g < 4096; g += 256) {
        int o = g >> 8, k = g & 255;
        recws[o * 264 + k] = recw[(og * 16 + o) * 256 + k];
        if (og < 8) f1ws[o * 264 + k] = f1w[(og * 16 + o) * 256 + k];
    }
    if (tid < 16) {
        b3s[tid] = b3[og * 16 + tid];
        recbs[tid] = recb[og * 16 + tid];
        if (og < 8) f1bs[tid] = f1b[og * 16 + tid];
    }
    if (tid < 48) tcbs[tid] = tcb[(tid >> 4) * 256 + og * 16 + (tid & 15)];
    f2s[tid] = f2w[tid];
    __syncthreads();

    float cur3 = 0.f, volt3 = 0.f, spk3 = 0.f;
    float curt = 0.f, voltt = 0.f, spkt = 0.f;
    float curr = 0.f, voltr = 0.f, spkr = 0.f;
    float curf = 0.f, voltf = 0.f, spkf = 0.f;
    float outacc = 0.f;

    // conv3 staging indices: 512 float4/chunk, 2 per thread
    const int k4a = tid >> 4;          // 0..15
    const int k4b = 16 + (tid >> 4);   // 16..31
    const int bls = tid & 15;

    for (int t = 0; t < T_STEPS; ++t) {
        // ---------- conv3: SMEM double-buffered chunks + serial FMA chain ----------
        {
            const float* tbase = g_p + (size_t)t * 73728 + bg * 64;
            // preload chunk 0
            float4 r0 = *(const float4*)(tbase + (size_t)(k4a) * 256 + bls * 4);
            float4 r1 = *(const float4*)(tbase + (size_t)(k4b) * 256 + bls * 4);
            *(float4*)(pb0 + (k4a * 16 + bls) * 4) = r0;
            *(float4*)(pb0 + (k4b * 16 + bls) * 4) = r1;
            __syncthreads();

            float a = 0.f;
            const float* wr = w3s + ol * 1160;
            for (int c = 0; c < 9; ++c) {
                float* cb = (c & 1) ? pb1 : pb0;
                float* nb = (c & 1) ? pb0 : pb1;
                float4 n0, n1;
                if (c < 8) {
                    n0 = *(const float4*)(tbase + (size_t)((c + 1) * 32 + k4a) * 256 + bls * 4);
                    n1 = *(const float4*)(tbase + (size_t)((c + 1) * 32 + k4b) * 256 + bls * 4);
                }
#pragma unroll
                for (int k4 = 0; k4 < 32; ++k4) {
                    float4 w = *(const float4*)(wr + (c * 32 + k4) * 4);
                    float4 x = *(const float4*)(cb + (k4 * 16 + bl) * 4);
                    a = __fmaf_rn(w.x, x.x, a);
                    a = __fmaf_rn(w.y, x.y, a);
                    a = __fmaf_rn(w.z, x.z, a);
                    a = __fmaf_rn(w.w, x.w, a);
                }
                if (c < 8) {
                    *(float4*)(nb + (k4a * 16 + bls) * 4) = n0;
                    *(float4*)(nb + (k4b * 16 + bls) * 4) = n1;
                }
                __syncthreads();
            }

            const float psp = __fadd_rn(a, b3s[ol]);
            lif_update(psp, cur3, volt3, spk3);
            g_s3[((t % 3) * 64 + (oc >> 2)) * 256 + b * 4 + (oc & 3)] = spk3;
        }
        gridbar_g(bg, 16);

        // ---------- stage fresh s3 slot into rolling SMEM cache ----------
        {
            const int slot = t % 3;
            const float* gsrc = g_s3 + slot * 16384 + bg * 64;
            float* sdst = s3c + slot * 4096;
#pragma unroll
            for (int j = 0; j < 4; ++j) {
                int idx = tid + j * 256;           // 0..1023
                int k4 = idx >> 4, b2 = idx & 15;
                *(float4*)(sdst + (k4 * 16 + b2) * 4) =
                    *(const float4*)(gsrc + k4 * 256 + b2 * 4);
            }
        }
        __syncthreads();

        // ---------- temporal conv (from SMEM) + LIF, fused recurrent + LIF ----------
        {
            const float* x0 = s3c + (t % 3) * 4096 + bl * 4;
            const float* x1 = s3c + ((t + 2) % 3) * 4096 + bl * 4;
            const float* x2 = s3c + ((t + 1) % 3) * 4096 + bl * 4;
            const float* w0 = tcws + (0 * 16 + ol) * 264;
            const float* w1v = tcws + (1 * 16 + ol) * 264;
            const float* w2v = tcws + (2 * 16 + ol) * 264;
            const bool h1 = (t >= 1), h2 = (t >= 2);

            float d0 = 0.f, d1 = 0.f, d2 = 0.f;
#pragma unroll 8
            for (int k4 = 0; k4 < 64; ++k4) {
                float4 a0 = *(const float4*)(x0 + k4 * 64);
                float4 q0 = *(const float4*)(w0 + k4 * 4);
                d0 = __fmaf_rn(q0.x, a0.x, d0);
                d0 = __fmaf_rn(q0.y, a0.y, d0);
                d0 = __fmaf_rn(q0.z, a0.z, d0);
                d0 = __fmaf_rn(q0.w, a0.w, d0);
                if (h1) {
                    float4 a1 = *(const float4*)(x1 + k4 * 64);
                    float4 q1 = *(const float4*)(w1v + k4 * 4);
                    d1 = __fmaf_rn(q1.x, a1.x, d1);
                    d1 = __fmaf_rn(q1.y, a1.y, d1);
                    d1 = __fmaf_rn(q1.z, a1.z, d1);
                    d1 = __fmaf_rn(q1.w, a1.w, d1);
                }
                if (h2) {
                    float4 a2 = *(const float4*)(x2 + k4 * 64);
                    float4 q2 = *(const float4*)(w2v + k4 * 4);
                    d2 = __fmaf_rn(q2.x, a2.x, d2);
                    d2 = __fmaf_rn(q2.y, a2.y, d2);
                    d2 = __fmaf_rn(q2.z, a2.z, d2);
                    d2 = __fmaf_rn(q2.w, a2.w, d2);
                }
            }
            float a = 0.f;
            a = __fadd_rn(a, __fadd_rn(d0, tcbs[0 * 16 + ol]));
            if (h1) a = __fadd_rn(a, __fadd_rn(d1, tcbs[1 * 16 + ol]));
            if (h2) a = __fadd_rn(a, __fadd_rn(d2, tcbs[2 * 16 + ol]));
            lif_update(a, curt, voltt, spkt);

            // recurrent: psp = (s_tc + dot) + bias
            float dotr = 0.f;
            if (t > 0)
                dotr = dot256pf(recws + ol * 264, g_sr + ((t & 1) ^ 1) * 16384 + b * 4);
            const float pr = __fadd_rn(__fadd_rn(spkt, dotr), recbs[ol]);
            lif_update(pr, curr, voltr, spkr);
            g_sr[((t & 1) * 64 + (oc >> 2)) * 256 + b * 4 + (oc & 3)] = spkr;
        }
        gridbar_g(bg, 16);

        // ---------- fc1 + LIF (og < 8 covers all 128 neurons) ----------
        if (og < 8) {
            const float d = dot256pf(f1ws + ol * 264, g_sr + (t & 1) * 16384 + b * 4);
            const float psp = __fadd_rn(d, f1bs[ol]);
            lif_update(psp, curf, voltf, spkf);
            g_sf[(oc >> 2) * 256 + b * 4 + (oc & 3)] = spkf;
        }
        gridbar_g(bg, 16);

        // ---------- fc2 + timestep weighting (og==0, 2 outputs x 16 b) ----------
        if (og == 0 && ol < 2) {
            const float d = dot128pf(f2s + ol * 128, g_sf + b * 4);
            outacc = __fadd_rn(outacc, __fmul_rn(d, tsw[t]));
        }
    }

    if (og == 0 && ol < 2) out[b * 2 + ol] = outacc;
}

// ============================================================================
extern "C" void kernel_launch(void* const* d_in, const int* in_sizes, int n_in,
                              void* d_out, int out_size)
{
    (void)in_sizes; (void)n_in; (void)out_size;
    const float* input = (const float*)d_in[0];
    const float* w1   = (const float*)d_in[1];
    const float* b1   = (const float*)d_in[2];
    const float* w2   = (const float*)d_in[3];
    const float* b2   = (const float*)d_in[4];
    const float* w3   = (const float*)d_in[5];
    const float* b3   = (const float*)d_in[6];
    const float* tcw  = (const float*)d_in[7];
    const float* tcb  = (const float*)d_in[8];
    const float* recw = (const float*)d_in[9];
    const float* recb = (const float*)d_in[10];
    const float* f1w  = (const float*)d_in[11];
    const float* f1b  = (const float*)d_in[12];
    const float* f2w  = (const float*)d_in[13];
    const float* tsw  = (const float*)d_in[14];
    float* out = (float*)d_out;

    cudaFuncSetAttribute(phaseA_kernel, cudaFuncAttributeMaxDynamicSharedMemorySize,
                         A_TOT * sizeof(float));
    cudaFuncSetAttribute(phaseB_kernel, cudaFuncAttributeMaxDynamicSharedMemorySize,
                         B_TOT * sizeof(float));

    phaseA_kernel<<<128, 128, A_TOT * sizeof(float)>>>(input, w1, b1, w2, b2);
    phaseB_kernel<<<64, 256, B_TOT * sizeof(float)>>>(w3, b3, tcw, tcb, recw, recb,
                                                      f1w, f1b, f2w, tsw, out);
}